// round 3
// baseline (speedup 1.0000x reference)
#include <cuda_runtime.h>

// Problem constants (fixed by setup_inputs)
#define NB 4
#define CC 128
#define HH 160
#define WW 320
#define DD 48

#define WT   128          // w-tile per CTA
#define RT   (WT + 48)    // right tile width incl. disparity halo = 176
#define CHS  64           // channels staged per pass
#define NTHR 128          // 4 warps: one per SMSP, each owns 12 disparities

// smem: L[CHS][WT] + R[CHS][RT] = 64*128 + 64*176 floats = 19456 floats = 77824 B
#define SMEM_FLOATS (CHS*WT + CHS*RT)

__global__ __launch_bounds__(NTHR, 2)
void cost_volume_kernel(const float* __restrict__ left,
                        const float* __restrict__ right,
                        float* __restrict__ out)
{
    extern __shared__ float smem[];
    float* Ls = smem;              // [CHS][WT]
    float* Rs = smem + CHS * WT;   // [CHS][RT]

    const int tid  = threadIdx.x;
    const int lane = tid & 31;
    const int warp = tid >> 5;          // 0..3
    const int w0   = blockIdx.x * WT;   // 0,128,256 (last tile partial)
    const int h    = blockIdx.y;
    const int n    = blockIdx.z;
    const int d0   = warp * 12;         // disparity group base

    // R smem window base for this thread: global w of Rs[i] is (w0-48+i).
    // acc[dj][wi] needs R at w0+4*lane+wi-(d0+dj) -> Rs index 4*lane-d0+48+wi-dj,
    // wi-dj in [-11,3]. Aligned window start:
    const int ib = 4 * lane - d0 + 36;  // multiple of 4; in [0,160]

    float acc[12][4];
    #pragma unroll
    for (int j = 0; j < 12; j++)
        #pragma unroll
        for (int i = 0; i < 4; i++) acc[j][i] = 0.0f;

    const size_t chan_stride = (size_t)HH * WW;

    for (int c0 = 0; c0 < CC; c0 += CHS) {
        // ---- stage left tile: CHS rows of 128 floats (float4, zero beyond W) ----
        {
            const float* lbase = left + ((size_t)(n * CC + c0) * HH + h) * WW;
            #pragma unroll 4
            for (int idx = tid; idx < CHS * (WT / 4); idx += NTHR) {
                int c  = idx / (WT / 4);
                int wq = (idx - c * (WT / 4)) * 4;
                int gw = w0 + wq;                    // multiple of 4; WW mult of 4
                float4 v = make_float4(0.f, 0.f, 0.f, 0.f);
                if (gw < WW) v = *(const float4*)(lbase + c * chan_stride + gw);
                *(float4*)(Ls + c * WT + wq) = v;
            }
        }
        // ---- stage right tile: CHS rows of 176 floats, halo zero-filled ----
        {
            const float* rbase = right + ((size_t)(n * CC + c0) * HH + h) * WW;
            #pragma unroll 4
            for (int idx = tid; idx < CHS * (RT / 4); idx += NTHR) {
                int c  = idx / (RT / 4);
                int wq = (idx - c * (RT / 4)) * 4;
                int gw = w0 - 48 + wq;               // multiple of 4
                float4 v = make_float4(0.f, 0.f, 0.f, 0.f);
                if (gw >= 0 && gw < WW) v = *(const float4*)(rbase + c * chan_stride + gw);
                *(float4*)(Rs + c * RT + wq) = v;
            }
        }
        __syncthreads();

        // ---- FFMA mainloop: per channel 5 LDS.128 -> 48 FMAs ----
        const float* lp = Ls + 4 * lane;
        const float* rp = Rs + ib;
        #pragma unroll 2
        for (int c = 0; c < CHS; c++) {
            float4 lv = *(const float4*)(lp + c * WT);
            float lw[4] = { lv.x, lv.y, lv.z, lv.w };
            float r[16];
            #pragma unroll
            for (int k = 0; k < 4; k++) {
                float4 rv = *(const float4*)(rp + c * RT + 4 * k);
                r[4*k+0] = rv.x; r[4*k+1] = rv.y; r[4*k+2] = rv.z; r[4*k+3] = rv.w;
            }
            #pragma unroll
            for (int dj = 0; dj < 12; dj++)
                #pragma unroll
                for (int wi = 0; wi < 4; wi++)
                    acc[dj][wi] = fmaf(lw[wi], r[wi - dj + 12], acc[dj][wi]);
        }
        __syncthreads();   // buffer reused next pass
    }

    // ---- store: float4 per disparity row; last tile guarded (gw mult of 4) ----
    const int gw = w0 + 4 * lane;
    if (gw < WW) {
        #pragma unroll
        for (int dj = 0; dj < 12; dj++) {
            int d = d0 + dj;
            float4 v = make_float4(acc[dj][0], acc[dj][1], acc[dj][2], acc[dj][3]);
            *(float4*)(out + (((size_t)(n * DD + d) * HH + h) * WW + gw)) = v;
        }
    }
}

extern "C" void kernel_launch(void* const* d_in, const int* in_sizes, int n_in,
                              void* d_out, int out_size)
{
    const float* left  = (const float*)d_in[0];
    const float* right = (const float*)d_in[1];
    float* out = (float*)d_out;

    cudaFuncSetAttribute(cost_volume_kernel,
                         cudaFuncAttributeMaxDynamicSharedMemorySize,
                         SMEM_FLOATS * (int)sizeof(float));

    dim3 grid((WW + WT - 1) / WT, HH, NB);   // (3, 160, 4)
    cost_volume_kernel<<<grid, NTHR, SMEM_FLOATS * sizeof(float)>>>(left, right, out);
}

// round 4
// speedup vs baseline: 1.0223x; 1.0223x over previous
#include <cuda_runtime.h>

// Problem constants (fixed by setup_inputs)
#define NB 4
#define CC 128
#define HH 160
#define WW 320
#define DD 48

#define WT   128          // w-tile per CTA
#define RT   (WT + 48)    // right tile width incl. disparity halo = 176
#define CHS  64           // channels staged per pass
#define NTHR 128          // 4 warps: one per SMSP, each owns 12 disparities

// smem: L[CHS][WT] + R[CHS][RT] = 64*128 + 64*176 floats = 19456 floats = 77824 B
#define SMEM_FLOATS (CHS*WT + CHS*RT)

__global__ __launch_bounds__(NTHR, 2)
void cost_volume_kernel(const float* __restrict__ left,
                        const float* __restrict__ right,
                        float* __restrict__ out)
{
    extern __shared__ float smem[];
    float* Ls = smem;              // [CHS][WT]
    float* Rs = smem + CHS * WT;   // [CHS][RT]

    const int tid  = threadIdx.x;
    const int lane = tid & 31;
    const int warp = tid >> 5;          // 0..3
    const int w0   = blockIdx.x * WT;   // 0,128,256 (last tile partial)
    const int h    = blockIdx.y;
    const int n    = blockIdx.z;
    const int d0   = warp * 12;         // disparity group base

    // R smem window base for this thread: global w of Rs[i] is (w0-48+i).
    // acc[dj][wi] needs R at w0+4*lane+wi-(d0+dj) -> Rs index 4*lane-d0+48+wi-dj,
    // wi-dj in [-11,3]. Aligned window start:
    const int ib = 4 * lane - d0 + 36;  // multiple of 4; in [0,160]

    float acc[12][4];
    #pragma unroll
    for (int j = 0; j < 12; j++)
        #pragma unroll
        for (int i = 0; i < 4; i++) acc[j][i] = 0.0f;

    const size_t chan_stride = (size_t)HH * WW;

    for (int c0 = 0; c0 < CC; c0 += CHS) {
        // ---- stage left tile: CHS rows of 128 floats (float4, zero beyond W) ----
        {
            const float* lbase = left + ((size_t)(n * CC + c0) * HH + h) * WW;
            #pragma unroll 4
            for (int idx = tid; idx < CHS * (WT / 4); idx += NTHR) {
                int c  = idx / (WT / 4);
                int wq = (idx - c * (WT / 4)) * 4;
                int gw = w0 + wq;                    // multiple of 4; WW mult of 4
                float4 v = make_float4(0.f, 0.f, 0.f, 0.f);
                if (gw < WW) v = *(const float4*)(lbase + c * chan_stride + gw);
                *(float4*)(Ls + c * WT + wq) = v;
            }
        }
        // ---- stage right tile: CHS rows of 176 floats, halo zero-filled ----
        {
            const float* rbase = right + ((size_t)(n * CC + c0) * HH + h) * WW;
            #pragma unroll 4
            for (int idx = tid; idx < CHS * (RT / 4); idx += NTHR) {
                int c  = idx / (RT / 4);
                int wq = (idx - c * (RT / 4)) * 4;
                int gw = w0 - 48 + wq;               // multiple of 4
                float4 v = make_float4(0.f, 0.f, 0.f, 0.f);
                if (gw >= 0 && gw < WW) v = *(const float4*)(rbase + c * chan_stride + gw);
                *(float4*)(Rs + c * RT + wq) = v;
            }
        }
        __syncthreads();

        // ---- FFMA mainloop: per channel 5 LDS.128 -> 48 FMAs ----
        const float* lp = Ls + 4 * lane;
        const float* rp = Rs + ib;
        #pragma unroll 2
        for (int c = 0; c < CHS; c++) {
            float4 lv = *(const float4*)(lp + c * WT);
            float lw[4] = { lv.x, lv.y, lv.z, lv.w };
            float r[16];
            #pragma unroll
            for (int k = 0; k < 4; k++) {
                float4 rv = *(const float4*)(rp + c * RT + 4 * k);
                r[4*k+0] = rv.x; r[4*k+1] = rv.y; r[4*k+2] = rv.z; r[4*k+3] = rv.w;
            }
            #pragma unroll
            for (int dj = 0; dj < 12; dj++)
                #pragma unroll
                for (int wi = 0; wi < 4; wi++)
                    acc[dj][wi] = fmaf(lw[wi], r[wi - dj + 12], acc[dj][wi]);
        }
        __syncthreads();   // buffer reused next pass
    }

    // ---- store: float4 per disparity row; last tile guarded (gw mult of 4) ----
    const int gw = w0 + 4 * lane;
    if (gw < WW) {
        #pragma unroll
        for (int dj = 0; dj < 12; dj++) {
            int d = d0 + dj;
            float4 v = make_float4(acc[dj][0], acc[dj][1], acc[dj][2], acc[dj][3]);
            *(float4*)(out + (((size_t)(n * DD + d) * HH + h) * WW + gw)) = v;
        }
    }
}

extern "C" void kernel_launch(void* const* d_in, const int* in_sizes, int n_in,
                              void* d_out, int out_size)
{
    const float* left  = (const float*)d_in[0];
    const float* right = (const float*)d_in[1];
    float* out = (float*)d_out;

    cudaFuncSetAttribute(cost_volume_kernel,
                         cudaFuncAttributeMaxDynamicSharedMemorySize,
                         SMEM_FLOATS * (int)sizeof(float));

    dim3 grid((WW + WT - 1) / WT, HH, NB);   // (3, 160, 4)
    cost_volume_kernel<<<grid, NTHR, SMEM_FLOATS * sizeof(float)>>>(left, right, out);
}

// round 5
// speedup vs baseline: 1.0225x; 1.0002x over previous
#include <cuda_runtime.h>

// Problem constants (fixed by setup_inputs)
#define NB 4
#define CC 128
#define HH 160
#define WW 320
#define DD 48

#define WT   128          // w-tile per CTA
#define RT   (WT + 48)    // right tile width incl. disparity halo = 176
#define CHS  64           // channels staged per pass
#define NTHR 128          // 4 warps: one per SMSP, each owns 12 disparities

// smem: L[CHS][WT] + R[CHS][RT] = 64*128 + 64*176 floats = 19456 floats = 77824 B
#define SMEM_FLOATS (CHS*WT + CHS*RT)

__global__ __launch_bounds__(NTHR, 2)
void cost_volume_kernel(const float* __restrict__ left,
                        const float* __restrict__ right,
                        float* __restrict__ out)
{
    extern __shared__ float smem[];
    float* Ls = smem;              // [CHS][WT]
    float* Rs = smem + CHS * WT;   // [CHS][RT]

    const int tid  = threadIdx.x;
    const int lane = tid & 31;
    const int warp = tid >> 5;          // 0..3
    const int w0   = blockIdx.x * WT;   // 0,128,256 (last tile partial)
    const int h    = blockIdx.y;
    const int n    = blockIdx.z;
    const int d0   = warp * 12;         // disparity group base

    // R smem window base for this thread: global w of Rs[i] is (w0-48+i).
    // acc[dj][wi] needs R at w0+4*lane+wi-(d0+dj) -> Rs index 4*lane-d0+48+wi-dj,
    // wi-dj in [-11,3]. Aligned window start:
    const int ib = 4 * lane - d0 + 36;  // multiple of 4; in [0,160]

    float acc[12][4];
    #pragma unroll
    for (int j = 0; j < 12; j++)
        #pragma unroll
        for (int i = 0; i < 4; i++) acc[j][i] = 0.0f;

    const size_t chan_stride = (size_t)HH * WW;

    for (int c0 = 0; c0 < CC; c0 += CHS) {
        // ---- stage left tile: CHS rows of 128 floats (float4, zero beyond W) ----
        {
            const float* lbase = left + ((size_t)(n * CC + c0) * HH + h) * WW;
            #pragma unroll 4
            for (int idx = tid; idx < CHS * (WT / 4); idx += NTHR) {
                int c  = idx / (WT / 4);
                int wq = (idx - c * (WT / 4)) * 4;
                int gw = w0 + wq;                    // multiple of 4; WW mult of 4
                float4 v = make_float4(0.f, 0.f, 0.f, 0.f);
                if (gw < WW) v = *(const float4*)(lbase + c * chan_stride + gw);
                *(float4*)(Ls + c * WT + wq) = v;
            }
        }
        // ---- stage right tile: CHS rows of 176 floats, halo zero-filled ----
        {
            const float* rbase = right + ((size_t)(n * CC + c0) * HH + h) * WW;
            #pragma unroll 4
            for (int idx = tid; idx < CHS * (RT / 4); idx += NTHR) {
                int c  = idx / (RT / 4);
                int wq = (idx - c * (RT / 4)) * 4;
                int gw = w0 - 48 + wq;               // multiple of 4
                float4 v = make_float4(0.f, 0.f, 0.f, 0.f);
                if (gw >= 0 && gw < WW) v = *(const float4*)(rbase + c * chan_stride + gw);
                *(float4*)(Rs + c * RT + wq) = v;
            }
        }
        __syncthreads();

        // ---- FFMA mainloop: per channel 5 LDS.128 -> 48 FMAs ----
        const float* lp = Ls + 4 * lane;
        const float* rp = Rs + ib;
        #pragma unroll 2
        for (int c = 0; c < CHS; c++) {
            float4 lv = *(const float4*)(lp + c * WT);
            float lw[4] = { lv.x, lv.y, lv.z, lv.w };
            float r[16];
            #pragma unroll
            for (int k = 0; k < 4; k++) {
                float4 rv = *(const float4*)(rp + c * RT + 4 * k);
                r[4*k+0] = rv.x; r[4*k+1] = rv.y; r[4*k+2] = rv.z; r[4*k+3] = rv.w;
            }
            #pragma unroll
            for (int dj = 0; dj < 12; dj++)
                #pragma unroll
                for (int wi = 0; wi < 4; wi++)
                    acc[dj][wi] = fmaf(lw[wi], r[wi - dj + 12], acc[dj][wi]);
        }
        __syncthreads();   // buffer reused next pass
    }

    // ---- store: float4 per disparity row; last tile guarded (gw mult of 4) ----
    const int gw = w0 + 4 * lane;
    if (gw < WW) {
        #pragma unroll
        for (int dj = 0; dj < 12; dj++) {
            int d = d0 + dj;
            float4 v = make_float4(acc[dj][0], acc[dj][1], acc[dj][2], acc[dj][3]);
            *(float4*)(out + (((size_t)(n * DD + d) * HH + h) * WW + gw)) = v;
        }
    }
}

extern "C" void kernel_launch(void* const* d_in, const int* in_sizes, int n_in,
                              void* d_out, int out_size)
{
    const float* left  = (const float*)d_in[0];
    const float* right = (const float*)d_in[1];
    float* out = (float*)d_out;

    cudaFuncSetAttribute(cost_volume_kernel,
                         cudaFuncAttributeMaxDynamicSharedMemorySize,
                         SMEM_FLOATS * (int)sizeof(float));

    dim3 grid((WW + WT - 1) / WT, HH, NB);   // (3, 160, 4)
    cost_volume_kernel<<<grid, NTHR, SMEM_FLOATS * sizeof(float)>>>(left, right, out);
}